// round 2
// baseline (speedup 1.0000x reference)
#include <cuda_runtime.h>
#include <math.h>

#define NN 10
#define CC 512
#define HW 1600
#define OC 128
#define IMG 40

// ---------------- scratch (device globals; no allocations allowed) ----------------
__device__ float g_NF[NN*CC*HW];      // normalized feats [n][c][hw]
__device__ float g_M [NN*CC*HW];      // NF * CSA         [n][c][hw]
__device__ float g_Ag[NN*CC*HW];      // gathered NF      [n][c][i] = NF[n][c][idx[n][i]]
__device__ float g_SIVraw[NN*CC];
__device__ float g_SIV[NN*CC];
__device__ float g_cm[NN*NN*HW];      // [n][m][hw]
__device__ float g_corr[NN*NN*NN];    // [n][m][p]
__device__ float g_sv[NN*NN];
__device__ float g_wv[NN*NN];
__device__ float g_CSA[NN*HW];
__device__ int   g_idx[NN*HW];
__device__ float g_W1t[OC*9*HW];      // [(o*9+t)][i]
__device__ float g_W2t[OC*9*OC];      // [(o*9+t)][c]
__device__ float g_Wt [NN*OC*9*CC];   // folded conv1 weights [n][(o*9+t)][c]
__device__ float g_Wts[NN*OC*CC];     // folded shortcut weights [n][o][c]
__device__ float g_H1[NN*OC*HW];      // relu(conv1)
__device__ float g_SC[NN*OC*HW];      // shortcut

// ---------------- helpers ----------------
__device__ __forceinline__ double blockReduceSumD(double v) {
    __shared__ double sh[32];
    int lane = threadIdx.x & 31, wid = threadIdx.x >> 5;
#pragma unroll
    for (int o = 16; o > 0; o >>= 1) v += __shfl_down_sync(0xffffffffu, v, o);
    if (lane == 0) sh[wid] = v;
    __syncthreads();
    if (wid == 0) {
        int nw = blockDim.x >> 5;
        v = (lane < nw) ? sh[lane] : 0.0;
#pragma unroll
        for (int o = 16; o > 0; o >>= 1) v += __shfl_down_sync(0xffffffffu, v, o);
    }
    return v; // valid in thread 0
}

// ---------------- 1: per-pixel L2 norm over C (fp32 squares, exact sum) -----------
__global__ void k_norm(const float* __restrict__ feats) {
    int n = blockIdx.y;
    int hw = blockIdx.x * 256 + threadIdx.x;
    if (hw >= HW) return;
    double ss = 0.0;
    for (int c = 0; c < CC; c++) {
        float v = feats[(n * CC + c) * HW + hw];
        float sq = v * v;                 // fp32-rounded square (matches materialized mul)
        ss += (double)sq;                 // exact accumulation
    }
    float S = (float)ss;
    float d = fmaxf(sqrtf(S), 1e-12f);
    for (int c = 0; c < CC; c++) {
        g_NF[(n * CC + c) * HW + hw] = feats[(n * CC + c) * HW + hw] / d;  // fp32 IEEE div
    }
}

// ---------------- 2: SIV raw = mean over hw of NF*SISM ----------------
__global__ void k_siv_raw(const float* __restrict__ sisms) {
    int b = blockIdx.x;              // n*CC + c
    int n = b >> 9;
    double s = 0.0;
    for (int k = threadIdx.x; k < HW; k += 256) {
        float pm = g_NF[b * HW + k] * sisms[n * HW + k];  // fp32-rounded product
        s += (double)pm;
    }
    s = blockReduceSumD(s);
    if (threadIdx.x == 0) {
        float S = (float)s;
        g_SIVraw[b] = S / 1600.0f;   // fp32 div (mean)
    }
}

// ---------------- 3: SIV l2 norm over C ----------------
__global__ void k_siv_norm() {
    int n = blockIdx.x, t = threadIdx.x;
    float v = g_SIVraw[n * CC + t];
    float sq = v * v;
    double s = blockReduceSumD((double)sq);
    __shared__ float s_d;
    if (t == 0) s_d = fmaxf(sqrtf((float)s), 1e-12f);
    __syncthreads();
    g_SIV[n * CC + t] = v / s_d;
}

// ---------------- 4: cm[n][m][k] = sum_c NF[n,c,k]*SIV[m,c] (dot: exact fp64) -----
__global__ void k_cm() {
    __shared__ float s_siv[NN * CC];
    int n = blockIdx.y;
    int k = blockIdx.x * 160 + threadIdx.x;
    for (int q = threadIdx.x; q < NN * CC; q += 160) s_siv[q] = g_SIV[q];
    __syncthreads();
    double acc[NN];
#pragma unroll
    for (int m = 0; m < NN; m++) acc[m] = 0.0;
    for (int c = 0; c < CC; c++) {
        double nf = (double)g_NF[(n * CC + c) * HW + k];
#pragma unroll
        for (int m = 0; m < NN; m++) acc[m] += nf * (double)s_siv[m * CC + c];
    }
#pragma unroll
    for (int m = 0; m < NN; m++) g_cm[(n * NN + m) * HW + k] = (float)acc[m];
}

// ---------------- 5: l2-normalize each cm row over k ----------------
__global__ void k_cm_norm() {
    int row = blockIdx.x;
    int base = row * HW;
    double ss = 0.0;
    for (int k = threadIdx.x; k < HW; k += 256) {
        float v = g_cm[base + k];
        float sq = v * v;
        ss += (double)sq;
    }
    ss = blockReduceSumD(ss);
    __shared__ float s_d;
    if (threadIdx.x == 0) s_d = fmaxf(sqrtf((float)ss), 1e-12f);
    __syncthreads();
    for (int k = threadIdx.x; k < HW; k += 256) g_cm[base + k] = g_cm[base + k] / s_d;
}

// ---------------- 6: corr[n][m][p] = dot(cm[n][m], cm[n][p]) (exact fp64, round) --
__global__ void k_corr() {
    int b = blockIdx.x;            // n*100 + m*10 + p
    int p = b % NN;
    int m = (b / NN) % NN;
    int n = b / (NN * NN);
    double s = 0.0;
    for (int k = threadIdx.x; k < HW; k += 256)
        s += (double)g_cm[(n * NN + m) * HW + k] * (double)g_cm[(n * NN + p) * HW + k];
    s = blockReduceSumD(s);
    if (threadIdx.x == 0) g_corr[b] = (float)s;   // fp32 materialization (matches einsum output)
}

// ---------------- 7: sv[n][m] = sum_p corr[n][m][p] ----------------
__global__ void k_sv() {
    int t = threadIdx.x;
    if (t >= NN * NN) return;
    double s = 0.0;
#pragma unroll
    for (int p = 0; p < NN; p++) s += (double)g_corr[t * NN + p];
    g_sv[t] = (float)s;
}

// ---------------- 8: softmax over m ----------------
__global__ void k_softmax() {
    int n = threadIdx.x;
    if (n >= NN) return;
    float mx = -1e30f;
    for (int m = 0; m < NN; m++) mx = fmaxf(mx, g_sv[n * NN + m]);
    float e[NN];
    double sum = 0.0;
    for (int m = 0; m < NN; m++) {
        float t = g_sv[n * NN + m] - mx;          // fp32 sub
        e[m] = (float)exp((double)t);             // ~correctly rounded expf
        sum += (double)e[m];
    }
    float S = (float)sum;
    for (int m = 0; m < NN; m++) g_wv[n * NN + m] = e[m] / S;  // fp32 div
}

// ---------------- 9: CSA + min-max normalize ----------------
__global__ void k_csa() {
    int n = blockIdx.x, tid = threadIdx.x;
    __shared__ float s_wv[NN];
    __shared__ float sc[HW];
    __shared__ float red[512];
    if (tid < NN) s_wv[tid] = g_wv[n * NN + tid];
    __syncthreads();
    float lmin = 1e30f, lmax = -1e30f;
    for (int k = tid; k < HW; k += 512) {
        double a = 0.0;
#pragma unroll
        for (int m = 0; m < NN; m++) {
            float pm = g_cm[(n * NN + m) * HW + k] * s_wv[m];  // fp32-rounded product
            a += (double)pm;
        }
        float raw = (float)a;
        sc[k] = raw;
        lmin = fminf(lmin, raw); lmax = fmaxf(lmax, raw);
    }
    red[tid] = lmin; __syncthreads();
    for (int s = 256; s > 0; s >>= 1) { if (tid < s) red[tid] = fminf(red[tid], red[tid + s]); __syncthreads(); }
    float mn = red[0]; __syncthreads();
    red[tid] = lmax; __syncthreads();
    for (int s = 256; s > 0; s >>= 1) { if (tid < s) red[tid] = fmaxf(red[tid], red[tid + s]); __syncthreads(); }
    float mx = red[0]; __syncthreads();
    float den = (mx - mn) + 1e-12f;               // fp32, left-assoc as reference
    for (int k = tid; k < HW; k += 512) {
        float num = sc[k] - mn;                   // fp32 sub
        g_CSA[n * HW + k] = num / den;            // fp32 IEEE div (monotone)
    }
}

// ---------------- 10: stable argsort descending (bitonic on 2048) ----------------
__global__ void k_sort() {
    __shared__ float key[2048];
    __shared__ int   idv[2048];
    int n = blockIdx.x, tid = threadIdx.x;
    for (int e = tid; e < 2048; e += 1024) {
        if (e < HW) { key[e] = g_CSA[n * HW + e]; idv[e] = e; }
        else        { key[e] = -1e30f;            idv[e] = e; }
    }
    __syncthreads();
    for (int k = 2; k <= 2048; k <<= 1) {
        for (int j = k >> 1; j > 0; j >>= 1) {
            for (int e = tid; e < 2048; e += 1024) {
                int ix = e ^ j;
                if (ix > e) {
                    float ka = key[e], kb = key[ix];
                    int ia = idv[e], ib = idv[ix];
                    bool up = ((e & k) == 0);
                    // "before": larger key first, ties by smaller index (stable)
                    bool b_before_a = (kb > ka) || (kb == ka && ib < ia);
                    bool dosw = up ? b_before_a : !b_before_a;
                    if (dosw) { key[e] = kb; key[ix] = ka; idv[e] = ib; idv[ix] = ia; }
                }
            }
            __syncthreads();
        }
    }
    for (int e = tid; e < HW; e += 1024) g_idx[n * HW + e] = idv[e];
}

// ---------------- 11: M = NF * CSA (broadcast over c) ----------------
__global__ void k_scaleM() {
    int i = blockIdx.x * 256 + threadIdx.x;
    if (i >= NN * CC * HW) return;
    int j = i % HW;
    int n = i / (CC * HW);
    g_M[i] = g_NF[i] * g_CSA[n * HW + j];
}

// ---------------- 12: gather Ag[n][c][i] = NF[n][c][idx[n][i]] ----------------
__global__ void k_gather() {
    int b = blockIdx.x;       // n*CC+c
    int n = b >> 9;
    for (int i = threadIdx.x; i < HW; i += 256)
        g_Ag[b * HW + i] = g_NF[b * HW + g_idx[n * HW + i]];
}

// ---------------- 13/14: weight transposes ----------------
__global__ void k_w1t(const float* __restrict__ w1) {
    int q = blockIdx.x * 256 + threadIdx.x;
    if (q >= OC * 9 * HW) return;
    int i = q % HW; int ot = q / HW; int o = ot / 9; int t = ot % 9;
    g_W1t[q] = w1[(o * HW + i) * 9 + t];
}
__global__ void k_w2t(const float* __restrict__ w2) {
    int q = blockIdx.x * 256 + threadIdx.x;
    if (q >= OC * 9 * OC) return;
    int c = q % OC; int ot = q / OC; int o = ot / 9; int t = ot % 9;
    g_W2t[q] = w2[(o * OC + c) * 9 + t];
}

// ---------------- 15: GEMM  C[M x 512] = A[M x 1600] * B[512 x 1600]^T per n ------
// mode 0: A=g_W1t (shared), C=g_Wt (batched).  mode 1: A=ws input, C=g_Wts (batched).
__global__ void k_gemm(int mode, const float* __restrict__ wsA, int M) {
    const int K = HW, Nc = CC;
    int n = blockIdx.z;
    const float* A = (mode == 0) ? g_W1t : wsA;
    const float* B = g_Ag + (size_t)n * CC * HW;
    float* C = (mode == 0) ? (g_Wt + (size_t)n * OC * 9 * CC) : (g_Wts + (size_t)n * OC * CC);
    int m0 = blockIdx.x * 64, n0 = blockIdx.y * 64;
    __shared__ float As[32 * 68];
    __shared__ float Bs[32 * 68];
    int tid = threadIdx.x, ty = tid / 16, tx = tid % 16;
    float acc[4][4] = {};
    for (int k0 = 0; k0 < K; k0 += 32) {
#pragma unroll
        for (int l = 0; l < 8; l++) {
            int e = tid + l * 256;
            int r = e >> 5, kk = e & 31;
            As[kk * 68 + r] = A[(size_t)(m0 + r) * K + k0 + kk];
            Bs[kk * 68 + r] = B[(size_t)(n0 + r) * K + k0 + kk];
        }
        __syncthreads();
#pragma unroll
        for (int kk = 0; kk < 32; kk++) {
            float4 a4 = *(const float4*)&As[kk * 68 + ty * 4];
            float4 b4 = *(const float4*)&Bs[kk * 68 + tx * 4];
            float av[4] = { a4.x, a4.y, a4.z, a4.w };
            float bv[4] = { b4.x, b4.y, b4.z, b4.w };
#pragma unroll
            for (int i = 0; i < 4; i++)
#pragma unroll
                for (int j = 0; j < 4; j++) acc[i][j] += av[i] * bv[j];
        }
        __syncthreads();
    }
#pragma unroll
    for (int i = 0; i < 4; i++)
#pragma unroll
        for (int j = 0; j < 4; j++)
            C[(size_t)(m0 + ty * 4 + i) * Nc + n0 + tx * 4 + j] = acc[i][j];
}

// ---------------- 16/17: implicit-GEMM 3x3 conv ----------------
// mode 0: conv1 (Cin=512, per-n weights g_Wt, fused 1x1 shortcut g_Wts) -> g_H1(relu), g_SC
// mode 1: conv2 (Cin=128, weights g_W2t) + g_SC, relu -> dout
__global__ void k_conv(int mode, const float* __restrict__ bias,
                       const float* __restrict__ bsc, float* __restrict__ dout) {
    int n = blockIdx.z;
    const float *X, *Wt, *Wsc = nullptr, *add = nullptr;
    float *o1, *o2 = nullptr;
    int Cin;
    if (mode == 0) {
        X = g_M + (size_t)n * CC * HW; Wt = g_Wt + (size_t)n * OC * 9 * CC; Cin = CC;
        Wsc = g_Wts + (size_t)n * OC * CC;
        o1 = g_H1 + (size_t)n * OC * HW; o2 = g_SC + (size_t)n * OC * HW;
    } else {
        X = g_H1 + (size_t)n * OC * HW; Wt = g_W2t; Cin = OC;
        add = g_SC + (size_t)n * OC * HW;
        o1 = dout + (size_t)n * OC * HW;
    }
    int o0 = blockIdx.x * 64, p0 = blockIdx.y * 64;
    int tid = threadIdx.x, ty = tid / 16, tx = tid % 16;
    __shared__ float sW[16 * 68];
    __shared__ float sB[16 * 68];
    float acc[4][4] = {};
    float accs[4][4] = {};

    for (int t = 0; t < 9; t++) {
        int dy = t / 3 - 1, dx = t % 3 - 1, off = dy * IMG + dx;
        for (int c0 = 0; c0 < Cin; c0 += 16) {
#pragma unroll
            for (int l = 0; l < 4; l++) {
                int e = tid + l * 256;
                int r = e >> 4, cc = e & 15;
                sW[cc * 68 + r] = Wt[(size_t)((o0 + r) * 9 + t) * Cin + c0 + cc];
                int pp = e & 63, cc2 = e >> 6;
                int p = p0 + pp;
                int px = p % IMG, py = p / IMG;
                int xs = px + dx, ysr = py + dy;
                float v = 0.f;
                if ((unsigned)xs < (unsigned)IMG && (unsigned)ysr < (unsigned)IMG)
                    v = X[(size_t)(c0 + cc2) * HW + p + off];
                sB[cc2 * 68 + pp] = v;
            }
            __syncthreads();
#pragma unroll
            for (int kk = 0; kk < 16; kk++) {
                float4 a4 = *(const float4*)&sW[kk * 68 + ty * 4];
                float4 b4 = *(const float4*)&sB[kk * 68 + tx * 4];
                float av[4] = { a4.x, a4.y, a4.z, a4.w };
                float bv[4] = { b4.x, b4.y, b4.z, b4.w };
#pragma unroll
                for (int i = 0; i < 4; i++)
#pragma unroll
                    for (int j = 0; j < 4; j++) acc[i][j] += av[i] * bv[j];
            }
            __syncthreads();
        }
    }
    if (mode == 0) {
        // fused 1x1 shortcut
        for (int c0 = 0; c0 < Cin; c0 += 16) {
#pragma unroll
            for (int l = 0; l < 4; l++) {
                int e = tid + l * 256;
                int r = e >> 4, cc = e & 15;
                sW[cc * 68 + r] = Wsc[(size_t)(o0 + r) * Cin + c0 + cc];
                int pp = e & 63, cc2 = e >> 6;
                sB[cc2 * 68 + pp] = X[(size_t)(c0 + cc2) * HW + p0 + pp];
            }
            __syncthreads();
#pragma unroll
            for (int kk = 0; kk < 16; kk++) {
                float4 a4 = *(const float4*)&sW[kk * 68 + ty * 4];
                float4 b4 = *(const float4*)&sB[kk * 68 + tx * 4];
                float av[4] = { a4.x, a4.y, a4.z, a4.w };
                float bv[4] = { b4.x, b4.y, b4.z, b4.w };
#pragma unroll
                for (int i = 0; i < 4; i++)
#pragma unroll
                    for (int j = 0; j < 4; j++) accs[i][j] += av[i] * bv[j];
            }
            __syncthreads();
        }
    }
#pragma unroll
    for (int i = 0; i < 4; i++) {
#pragma unroll
        for (int j = 0; j < 4; j++) {
            int o = o0 + ty * 4 + i, p = p0 + tx * 4 + j;
            float v = acc[i][j] + bias[o];
            if (mode == 1) {
                v += add[(size_t)o * HW + p];
                o1[(size_t)o * HW + p] = fmaxf(v, 0.f);
            } else {
                o1[(size_t)o * HW + p] = fmaxf(v, 0.f);
                o2[(size_t)o * HW + p] = accs[i][j] + bsc[o];
            }
        }
    }
}

// ---------------- launch ----------------
extern "C" void kernel_launch(void* const* d_in, const int* in_sizes, int n_in,
                              void* d_out, int out_size) {
    const float *feats = nullptr, *sisms = nullptr, *w1 = nullptr, *w2 = nullptr, *ws = nullptr;
    const float *b1 = nullptr, *b2 = nullptr, *bs = nullptr;
    for (int i = 0; i < n_in; i++) {
        int s = in_sizes[i];
        const float* p = (const float*)d_in[i];
        if (s == NN * CC * HW) feats = p;
        else if (s == NN * HW) sisms = p;
        else if (s == OC * HW * 9) w1 = p;
        else if (s == OC * OC * 9) w2 = p;
        else if (s == OC * HW) ws = p;
        else if (s == OC) { if (!b1) b1 = p; else if (!b2) b2 = p; else bs = p; }
    }
    float* out = (float*)d_out;

    k_norm<<<dim3((HW + 255) / 256, NN), 256>>>(feats);
    k_siv_raw<<<NN * CC, 256>>>(sisms);
    k_siv_norm<<<NN, CC>>>();
    k_cm<<<dim3(HW / 160, NN), 160>>>();
    k_cm_norm<<<NN * NN, 256>>>();
    k_corr<<<NN * NN * NN, 256>>>();
    k_sv<<<1, 128>>>();
    k_softmax<<<1, 16>>>();
    k_csa<<<NN, 512>>>();
    k_sort<<<NN, 1024>>>();
    k_scaleM<<<(NN * CC * HW + 255) / 256, 256>>>();
    k_gather<<<NN * CC, 256>>>();
    k_w1t<<<(OC * 9 * HW + 255) / 256, 256>>>(w1);
    k_w2t<<<(OC * 9 * OC + 255) / 256, 256>>>(w2);
    k_gemm<<<dim3((OC * 9) / 64, CC / 64, NN), 256>>>(0, nullptr, OC * 9);  // folded conv1 weights
    k_gemm<<<dim3(OC / 64, CC / 64, NN), 256>>>(1, ws, OC);                 // folded shortcut weights
    k_conv<<<dim3(OC / 64, HW / 64, NN), 256>>>(0, b1, bs, nullptr);        // conv1 (+shortcut)
    k_conv<<<dim3(OC / 64, HW / 64, NN), 256>>>(1, b2, nullptr, out);       // conv2 + add + relu
    (void)out_size; (void)n_in;
}